// round 8
// baseline (speedup 1.0000x reference)
#include <cuda_runtime.h>
#include <cuda_bf16.h>
#include <cstdint>

#define BH   64
#define SEQ  8192
#define HD   128
#define SP   7936
#define KEEP 256
#define KTOP 192
#define LOCQ 64

// ---------------- scratch (device globals: allocation-free) ----------------
__device__ __nv_bfloat16 g_X [(size_t)BH * 256 * SP];   // non_k|non_v, [head][c][t]
__device__ __nv_bfloat16 g_Y0[(size_t)BH * 512 * SP];   // silu(conv0)
__device__ __nv_bfloat16 g_L [(size_t)BH * 256 * SP];   // logits -> softmax weights
__device__ __nv_bfloat16 g_A0[512 * 768];               // conv0 W, k = dk*256+c
__device__ __nv_bfloat16 g_A1[256 * 1536];              // conv1 W, k = dk*512+c
__device__ int g_hh    [BH * KEEP];
__device__ int g_non   [BH * SP];
__device__ int g_res   [BH * 256];                      // residual non-indices, ascending
__device__ int g_noninv[BH * SEQ];                      // seq pos -> non index

// ---------------- helpers ----------------
__device__ __forceinline__ uint32_t smem_u32(const void* p) {
    return (uint32_t)__cvta_generic_to_shared(p);
}
__device__ __forceinline__ void ldsm_x4(uint32_t* r, uint32_t a) {
    asm volatile("ldmatrix.sync.aligned.m8n8.x4.shared.b16 {%0,%1,%2,%3}, [%4];"
                 : "=r"(r[0]), "=r"(r[1]), "=r"(r[2]), "=r"(r[3]) : "r"(a));
}
__device__ __forceinline__ void ldsm_x2t(uint32_t* r, uint32_t a) {
    asm volatile("ldmatrix.sync.aligned.m8n8.x2.trans.shared.b16 {%0,%1}, [%2];"
                 : "=r"(r[0]), "=r"(r[1]) : "r"(a));
}
__device__ __forceinline__ void ldsm_x2(uint32_t* r, uint32_t a) {
    asm volatile("ldmatrix.sync.aligned.m8n8.x2.shared.b16 {%0,%1}, [%2];"
                 : "=r"(r[0]), "=r"(r[1]) : "r"(a));
}
__device__ __forceinline__ void mma16816(float* c, const uint32_t* a, const uint32_t* b) {
    asm volatile(
        "mma.sync.aligned.m16n8k16.row.col.f32.bf16.bf16.f32 "
        "{%0,%1,%2,%3}, {%4,%5,%6,%7}, {%8,%9}, {%0,%1,%2,%3};\n"
        : "+f"(c[0]), "+f"(c[1]), "+f"(c[2]), "+f"(c[3])
        : "r"(a[0]), "r"(a[1]), "r"(a[2]), "r"(a[3]), "r"(b[0]), "r"(b[1]));
}
__device__ __forceinline__ float silu_f(float x) { return x / (1.f + __expf(-x)); }

// ---------------- K1: repack conv weights to bf16 im2col ----------------
__global__ void __launch_bounds__(256) prep_weights_kernel(const float* __restrict__ w0,
                                                           const float* __restrict__ w1) {
    int idx = blockIdx.x * 256 + threadIdx.x;
    if (idx < 512 * 768) {
        int o = idx / 768, k = idx % 768, dk = k / 256, c = k % 256;
        g_A0[idx] = __float2bfloat16(w0[(o * 256 + c) * 3 + dk]);
    } else {
        int i2 = idx - 512 * 768;
        if (i2 < 256 * 1536) {
            int o = i2 / 1536, k = i2 % 1536, dk = k / 512, c = k % 512;
            g_A1[i2] = __float2bfloat16(w1[(o * 512 + c) * 3 + dk]);
        }
    }
}

// ---------------- K2: exact selection (radix top-k, jax tie semantics) ------
__shared__ uint32_t      s_key [SEQ];
__shared__ unsigned char s_mask[SEQ];
__shared__ int           s_scan[257];
__shared__ int           s_hist[256];
__shared__ uint32_t      s_pref;
__shared__ int           s_rem, s_cnt;

__device__ void radix_topk(int limit, int K, uint32_t* p_thr, int* p_cntgt) {
    const int tid = threadIdx.x;
    if (tid == 0) { s_pref = 0u; s_rem = K; s_cnt = 0; }
    __syncthreads();
    for (int shift = 24; shift >= 0; shift -= 8) {
        s_hist[tid] = 0;
        __syncthreads();
        uint32_t pref  = s_pref;
        uint32_t hmask = (shift == 24) ? 0u : (0xFFFFFFFFu << (shift + 8));
        for (int i = tid; i < limit; i += 256) {
            uint32_t k = s_key[i];
            if (((k ^ pref) & hmask) == 0u) atomicAdd(&s_hist[(k >> shift) & 255], 1);
        }
        __syncthreads();
        if (tid == 0) {
            int accv = 0, b = 255;
            for (; b > 0; b--) {
                if (accv + s_hist[b] >= s_rem) break;
                accv += s_hist[b];
            }
            s_pref |= ((uint32_t)b << shift);
            s_rem -= accv;
            s_cnt += accv;
        }
        __syncthreads();
    }
    *p_thr = s_pref;
    *p_cntgt = s_cnt;
    __syncthreads();
}

__global__ void __launch_bounds__(256) select_kernel(const float* __restrict__ scores) {
    const int head = blockIdx.x, tid = threadIdx.x;
    const float* sc = scores + (size_t)head * SEQ;
    for (int i = tid; i < SEQ; i += 256) {
        uint32_t b = __float_as_uint(sc[i]);
        s_key[i] = (b & 0x80000000u) ? ~b : (b | 0x80000000u);  // order-preserving
        s_mask[i] = 0;
    }
    __syncthreads();

    // --- selection 1: top KTOP over [0, SEQ-LOCQ) ---
    uint32_t thr; int cgt;
    radix_topk(SEQ - LOCQ, KTOP, &thr, &cgt);
    for (int i = tid; i < SEQ - LOCQ; i += 256)
        if (s_key[i] > thr) s_mask[i] = 1;
    for (int i = SEQ - LOCQ + tid; i < SEQ; i += 256) s_mask[i] = 1;
    __syncthreads();
    if (tid == 0) {
        int need = KTOP - cgt, taken = 0;
        for (int i = 0; i < SEQ - LOCQ && taken < need; i++)
            if (s_key[i] == thr) { s_mask[i] = 1; taken++; }
    }
    __syncthreads();

    // --- stable compaction into hh / non lists ---
    const int base = tid * 32;
    int cnt = 0;
#pragma unroll
    for (int j = 0; j < 32; j++) cnt += s_mask[base + j];
    s_scan[tid] = cnt;
    __syncthreads();
    if (tid == 0) {
        int a = 0;
        for (int k = 0; k < 256; k++) { int t = s_scan[k]; s_scan[k] = a; a += t; }
    }
    __syncthreads();
    {
        int ho = s_scan[tid], no = base - s_scan[tid];
        for (int j = 0; j < 32; j++) {
            int i = base + j;
            if (s_mask[i]) { g_hh[head * KEEP + (ho++)] = i; }
            else { g_noninv[head * SEQ + i] = no; g_non[head * SP + (no++)] = i; }
        }
    }
    __syncthreads();

    // --- selection 2: top 256 among non positions (zero out hh keys) ---
    for (int i = tid; i < SEQ; i += 256)
        if (s_mask[i]) s_key[i] = 0u;   // all real keys >= 0x80000000 > 0
    __syncthreads();
    uint32_t thr2; int cgt2;
    radix_topk(SEQ, 256, &thr2, &cgt2);
    for (int i = tid; i < SEQ; i += 256)
        s_mask[i] = (s_key[i] > thr2) ? 1 : 0;
    __syncthreads();
    if (tid == 0) {
        int need = 256 - cgt2, taken = 0;
        for (int i = 0; i < SEQ && taken < need; i++)
            if (s_key[i] == thr2) { s_mask[i] = 1; taken++; }
    }
    __syncthreads();
    cnt = 0;
#pragma unroll
    for (int j = 0; j < 32; j++) cnt += s_mask[base + j];
    s_scan[tid] = cnt;
    __syncthreads();
    if (tid == 0) {
        int a = 0;
        for (int k = 0; k < 256; k++) { int t = s_scan[k]; s_scan[k] = a; a += t; }
    }
    __syncthreads();
    {
        int ro = s_scan[tid];
        for (int j = 0; j < 32; j++) {
            int i = base + j;
            if (s_mask[i]) g_res[head * 256 + (ro++)] = g_noninv[head * SEQ + i];
        }
    }
}

// ---------------- K3: gather non_k|non_v -> bf16 X[c][t] (transposed) -------
__global__ void __launch_bounds__(256) gather_x_kernel(const float* __restrict__ pk,
                                                       const float* __restrict__ pv) {
    const int head = blockIdx.x / 124;
    const int t0 = (blockIdx.x % 124) * 64;
    const int tid = threadIdx.x;
    __shared__ __nv_bfloat16 tileS[128][66];
    __shared__ int spos[64];
    if (tid < 64) spos[tid] = g_non[head * SP + t0 + tid];
    __syncthreads();
    const float* srcs[2] = { pk, pv };
#pragma unroll
    for (int half = 0; half < 2; half++) {
        const float* src = srcs[half];
#pragma unroll 4
        for (int it = 0; it < 32; it++) {
            int idx = it * 256 + tid, tl = idx >> 7, dd = idx & 127;
            tileS[dd][tl] = __float2bfloat16(src[((size_t)head * SEQ + spos[tl]) * HD + dd]);
        }
        __syncthreads();
#pragma unroll 4
        for (int it = 0; it < 32; it++) {
            int idx = it * 256 + tid, c = idx >> 6, tl = idx & 63;
            g_X[((size_t)head * 256 + half * 128 + c) * SP + t0 + tl] = tileS[c][tl];
        }
        __syncthreads();
    }
}

// ---------------- K4: exact fp32 hh gather to output rows [0,256) ----------
__global__ void __launch_bounds__(256) hh_out_kernel(const float* __restrict__ pk,
                                                     const float* __restrict__ pv,
                                                     float* __restrict__ out) {
    const int head = blockIdx.x, tid = threadIdx.x;
    __shared__ int pos[KEEP];
    if (tid < KEEP) pos[tid] = g_hh[head * KEEP + tid];
    __syncthreads();
    const size_t vofs = (size_t)BH * 512 * HD;
    for (int idx = tid; idx < KEEP * HD; idx += 256) {
        int j = idx >> 7, dd = idx & 127;
        size_t src = ((size_t)head * SEQ + pos[j]) * HD + dd;
        size_t dst = ((size_t)head * 512 + j) * HD + dd;
        out[dst] = pk[src];
        out[vofs + dst] = pv[src];
    }
}

// ---------------- K5/K6: conv-as-GEMM 128x128x32, mma.sync, bias+SiLU ------
template <int CIN, int MTOT>
__global__ void __launch_bounds__(256) conv_gemm_kernel(const float* __restrict__ bias) {
    constexpr int KTOT = 3 * CIN;
    const int head = blockIdx.z;
    const int m0 = blockIdx.y * 128;
    const int t0 = blockIdx.x * 128;
    const __nv_bfloat16* __restrict__ A    = (CIN == 256) ? g_A0 : g_A1;
    const __nv_bfloat16* __restrict__ Xin  = (CIN == 256) ? g_X : g_Y0;
    __nv_bfloat16* __restrict__       Yout = (CIN == 256) ? g_Y0 : g_L;
    const __nv_bfloat16* Xh = Xin + (size_t)head * CIN * SP;

    __shared__ __nv_bfloat16 As[128][40];
    __shared__ __nv_bfloat16 Bs[32][136];

    const int tid = threadIdx.x, lane = tid & 31, wid = tid >> 5;
    const int wm = wid >> 2, wn = wid & 3;

    float acc[4][4][4];
#pragma unroll
    for (int i = 0; i < 4; i++)
#pragma unroll
        for (int j = 0; j < 4; j++)
#pragma unroll
            for (int k = 0; k < 4; k++) acc[i][j][k] = 0.f;

    for (int k0 = 0; k0 < KTOT; k0 += 32) {
        const int dk = k0 / CIN;
        const int cbase = k0 - dk * CIN;
#pragma unroll
        for (int r = 0; r < 16; r++) {
            int idx = r * 256 + tid, row = idx >> 5, kk = idx & 31;
            As[row][kk] = A[(size_t)(m0 + row) * KTOT + k0 + kk];
        }
#pragma unroll
        for (int r = 0; r < 16; r++) {
            int idx = r * 256 + tid, kk = idx >> 7, tl = idx & 127;
            int t = t0 + tl + dk - 1;  // pad 1
            __nv_bfloat16 v = __float2bfloat16(0.f);
            if (t >= 0 && t < SP) v = Xh[(size_t)(cbase + kk) * SP + t];
            Bs[kk][tl] = v;
        }
        __syncthreads();
#pragma unroll
        for (int ks = 0; ks < 2; ks++) {
            const int kr = ks * 16;
            uint32_t af[4][4], bfr[4][2];
#pragma unroll
            for (int mf = 0; mf < 4; mf++)
                ldsm_x4(af[mf], smem_u32(&As[wm * 64 + mf * 16 + (lane & 15)]
                                            [kr + ((lane & 16) ? 8 : 0)]));
#pragma unroll
            for (int nf = 0; nf < 4; nf++)
                ldsm_x2t(bfr[nf], smem_u32(&Bs[kr + (lane & 15)][wn * 32 + nf * 8]));
#pragma unroll
            for (int mf = 0; mf < 4; mf++)
#pragma unroll
                for (int nf = 0; nf < 4; nf++)
                    mma16816(acc[mf][nf], af[mf], bfr[nf]);
        }
        __syncthreads();
    }
    // epilogue: bias + SiLU, bf16 store
#pragma unroll
    for (int mf = 0; mf < 4; mf++) {
        int rb = m0 + wm * 64 + mf * 16 + (lane >> 2);
#pragma unroll
        for (int half = 0; half < 2; half++) {
            int r = rb + half * 8;
            float b = bias[r];
#pragma unroll
            for (int nf = 0; nf < 4; nf++) {
                int tc = t0 + wn * 32 + nf * 8 + (lane & 3) * 2;
                __nv_bfloat162 p;
                p.x = __float2bfloat16(silu_f(acc[mf][nf][half * 2 + 0] + b));
                p.y = __float2bfloat16(silu_f(acc[mf][nf][half * 2 + 1] + b));
                *reinterpret_cast<__nv_bfloat162*>(&Yout[((size_t)head * MTOT + r) * SP + tc]) = p;
            }
        }
    }
}

// ---------------- K7: softmax row (x normalizer), in place ------------------
__global__ void __launch_bounds__(256) softmax_kernel(const float* __restrict__ norm) {
    const int head = blockIdx.y, m = blockIdx.x, tid = threadIdx.x;
    __nv_bfloat16* row = g_L + ((size_t)head * 256 + m) * SP;
    __shared__ float red[8];
    __shared__ float smax, ssum;
    float mx = -1e30f;
    for (int i = tid; i < SP; i += 256) mx = fmaxf(mx, __bfloat162float(row[i]));
#pragma unroll
    for (int o = 16; o > 0; o >>= 1) mx = fmaxf(mx, __shfl_xor_sync(0xffffffffu, mx, o));
    if ((tid & 31) == 0) red[tid >> 5] = mx;
    __syncthreads();
    if (tid == 0) {
        float v = red[0];
        for (int i = 1; i < 8; i++) v = fmaxf(v, red[i]);
        smax = v;
    }
    __syncthreads();
    mx = smax;
    float s = 0.f;
    for (int i = tid; i < SP; i += 256) s += __expf(__bfloat162float(row[i]) - mx);
#pragma unroll
    for (int o = 16; o > 0; o >>= 1) s += __shfl_xor_sync(0xffffffffu, s, o);
    if ((tid & 31) == 0) red[tid >> 5] = s;
    __syncthreads();
    if (tid == 0) {
        float v = 0.f;
        for (int i = 0; i < 8; i++) v += red[i];
        ssum = v;
    }
    __syncthreads();
    const float scale = norm[0] / ssum;
    for (int i = tid; i < SP; i += 256)
        row[i] = __float2bfloat16(__expf(__bfloat162float(row[i]) - mx) * scale);
}

// ---------------- K8: merged NT GEMM C[m][n] = sum_t w[m,t] * X[n,t] --------
__global__ void __launch_bounds__(256) merged_gemm_kernel(float* __restrict__ out) {
    const int head = blockIdx.z;
    const int n0 = blockIdx.x * 128;   // 0 -> keys, 128 -> vals
    const int m0 = blockIdx.y * 128;
    const __nv_bfloat16* Ah = g_L + (size_t)head * 256 * SP;
    const __nv_bfloat16* Bh = g_X + (size_t)head * 256 * SP;

    __shared__ __nv_bfloat16 As[128][40];
    __shared__ __nv_bfloat16 Bs[128][40];

    const int tid = threadIdx.x, lane = tid & 31, wid = tid >> 5;
    const int wm = wid >> 2, wn = wid & 3;

    float acc[4][4][4];
#pragma unroll
    for (int i = 0; i < 4; i++)
#pragma unroll
        for (int j = 0; j < 4; j++)
#pragma unroll
            for (int k = 0; k < 4; k++) acc[i][j][k] = 0.f;

    for (int k0 = 0; k0 < SP; k0 += 32) {
#pragma unroll
        for (int r = 0; r < 16; r++) {
            int idx = r * 256 + tid, row = idx >> 5, kk = idx & 31;
            As[row][kk] = Ah[(size_t)(m0 + row) * SP + k0 + kk];
            Bs[row][kk] = Bh[(size_t)(n0 + row) * SP + k0 + kk];
        }
        __syncthreads();
#pragma unroll
        for (int ks = 0; ks < 2; ks++) {
            const int kr = ks * 16;
            uint32_t af[4][4], bfr[4][2];
#pragma unroll
            for (int mf = 0; mf < 4; mf++)
                ldsm_x4(af[mf], smem_u32(&As[wm * 64 + mf * 16 + (lane & 15)]
                                            [kr + ((lane & 16) ? 8 : 0)]));
#pragma unroll
            for (int nf = 0; nf < 4; nf++)
                ldsm_x2(bfr[nf], smem_u32(&Bs[wn * 32 + nf * 8 + (lane & 7)]
                                             [kr + ((lane & 8) ? 8 : 0)]));
#pragma unroll
            for (int mf = 0; mf < 4; mf++)
#pragma unroll
                for (int nf = 0; nf < 4; nf++)
                    mma16816(acc[mf][nf], af[mf], bfr[nf]);
        }
        __syncthreads();
    }
    // epilogue: write fp32 to keys (n<128) or vals (n>=128), rows 256+m
    const size_t vofs = (size_t)BH * 512 * HD;
    const size_t hofs = (n0 >= 128) ? vofs : 0;
    const int dbase = (n0 >= 128) ? (n0 - 128) : n0;  // 0 either way, kept for clarity
#pragma unroll
    for (int mf = 0; mf < 4; mf++) {
        int gm = m0 + wm * 64 + mf * 16 + (lane >> 2);
#pragma unroll
        for (int half = 0; half < 2; half++) {
            int r = gm + half * 8;
            float* dst_row = out + hofs + ((size_t)head * 512 + 256 + r) * HD;
#pragma unroll
            for (int nf = 0; nf < 4; nf++) {
                int d = dbase + wn * 32 + nf * 8 + (lane & 3) * 2;
                dst_row[d + 0] = acc[mf][nf][half * 2 + 0];
                dst_row[d + 1] = acc[mf][nf][half * 2 + 1];
            }
        }
    }
}

// ---------------- K9: fp32 residual add (1 - normalizer) -------------------
__global__ void __launch_bounds__(256) residual_kernel(const float* __restrict__ pk,
                                                       const float* __restrict__ pv,
                                                       const float* __restrict__ norm,
                                                       float* __restrict__ out) {
    const int head = blockIdx.x, tid = threadIdx.x;
    const float c = 1.f - norm[0];
    const size_t vofs = (size_t)BH * 512 * HD;
    __shared__ int pos[256];
    if (tid < 256) pos[tid] = g_non[head * SP + g_res[head * 256 + tid]];
    __syncthreads();
    for (int idx = tid; idx < 256 * HD; idx += 256) {
        int m = idx >> 7, d = idx & 127;
        size_t src = ((size_t)head * SEQ + pos[m]) * HD + d;
        size_t dst = ((size_t)head * 512 + 256 + m) * HD + d;
        out[dst]        += c * pk[src];
        out[vofs + dst] += c * pv[src];
    }
}

// ---------------- launch ----------------
extern "C" void kernel_launch(void* const* d_in, const int* in_sizes, int n_in,
                              void* d_out, int out_size) {
    const float* pk = (const float*)d_in[0];
    const float* pv = (const float*)d_in[1];
    const float* sc = (const float*)d_in[2];
    const float* w0 = (const float*)d_in[3];
    const float* b0 = (const float*)d_in[4];
    const float* w1 = (const float*)d_in[5];
    const float* b1 = (const float*)d_in[6];
    const float* nz = (const float*)d_in[7];
    float* out = (float*)d_out;

    prep_weights_kernel<<<3072, 256>>>(w0, w1);
    select_kernel<<<64, 256>>>(sc);
    gather_x_kernel<<<64 * 124, 256>>>(pk, pv);
    hh_out_kernel<<<64, 256>>>(pk, pv, out);
    conv_gemm_kernel<256, 512><<<dim3(62, 4, 64), 256>>>(b0);
    conv_gemm_kernel<512, 256><<<dim3(62, 2, 64), 256>>>(b1);
    softmax_kernel<<<dim3(256, 64), 256>>>(nz);
    merged_gemm_kernel<<<dim3(2, 2, 64), 256>>>(out);
    residual_kernel<<<64, 256>>>(pk, pv, nz, out);
}

// round 11
// speedup vs baseline: 1.7779x; 1.7779x over previous
#include <cuda_runtime.h>
#include <cuda_bf16.h>
#include <cstdint>

#define BH   64
#define SEQ  8192
#define HD   128
#define SP   7936
#define KEEP 256
#define KTOP 192
#define LOCQ 64
#define NCHK 31     // SP / 256

// ---------------- scratch (device globals: allocation-free) ----------------
// Activations are TIME-MAJOR: row t holds all channels contiguously.
__device__ __align__(128) __nv_bfloat16 g_X [(size_t)BH * SP * 256];   // [head][t][256] (k|v)
__device__ __align__(128) __nv_bfloat16 g_Y0[(size_t)BH * SP * 512];   // [head][t][512]
__device__ __align__(128) __nv_bfloat16 g_L [(size_t)BH * SP * 256];   // [head][t][256]
__device__ __align__(128) __nv_bfloat16 g_A0[512 * 768];               // conv0 W, k = dk*256+c
__device__ __align__(128) __nv_bfloat16 g_A1[256 * 1536];              // conv1 W, k = dk*512+c
__device__ int   g_hh    [BH * KEEP];
__device__ int   g_non   [BH * SP];
__device__ int   g_res   [BH * 256];
__device__ int   g_noninv[BH * SEQ];
__device__ float g_pm [BH * NCHK * 256];                // partial max
__device__ float g_ps [BH * NCHK * 256];                // partial sum
__device__ float g_rm [BH * 256];                       // col max
__device__ float g_rs [BH * 256];                       // col scale = nz / sum

// ---------------- helpers ----------------
__device__ __forceinline__ uint32_t smem_u32(const void* p) {
    return (uint32_t)__cvta_generic_to_shared(p);
}
__device__ __forceinline__ void ldsm_x4(uint32_t* r, uint32_t a) {
    asm volatile("ldmatrix.sync.aligned.m8n8.x4.shared.b16 {%0,%1,%2,%3}, [%4];"
                 : "=r"(r[0]), "=r"(r[1]), "=r"(r[2]), "=r"(r[3]) : "r"(a));
}
__device__ __forceinline__ void ldsm_x4t(uint32_t* r, uint32_t a) {
    asm volatile("ldmatrix.sync.aligned.m8n8.x4.trans.shared.b16 {%0,%1,%2,%3}, [%4];"
                 : "=r"(r[0]), "=r"(r[1]), "=r"(r[2]), "=r"(r[3]) : "r"(a));
}
__device__ __forceinline__ void ldsm_x2t(uint32_t* r, uint32_t a) {
    asm volatile("ldmatrix.sync.aligned.m8n8.x2.trans.shared.b16 {%0,%1}, [%2];"
                 : "=r"(r[0]), "=r"(r[1]) : "r"(a));
}
__device__ __forceinline__ void ldsm_x2(uint32_t* r, uint32_t a) {
    asm volatile("ldmatrix.sync.aligned.m8n8.x2.shared.b16 {%0,%1}, [%2];"
                 : "=r"(r[0]), "=r"(r[1]) : "r"(a));
}
__device__ __forceinline__ void mma16816(float* c, const uint32_t* a, const uint32_t* b) {
    asm volatile(
        "mma.sync.aligned.m16n8k16.row.col.f32.bf16.bf16.f32 "
        "{%0,%1,%2,%3}, {%4,%5,%6,%7}, {%8,%9}, {%0,%1,%2,%3};\n"
        : "+f"(c[0]), "+f"(c[1]), "+f"(c[2]), "+f"(c[3])
        : "r"(a[0]), "r"(a[1]), "r"(a[2]), "r"(a[3]), "r"(b[0]), "r"(b[1]));
}
__device__ __forceinline__ void cpa16(uint32_t d, const void* s, int sz) {
    asm volatile("cp.async.cg.shared.global [%0], [%1], 16, %2;"
                 :: "r"(d), "l"(s), "r"(sz));
}
__device__ __forceinline__ void cpa_commit() {
    asm volatile("cp.async.commit_group;");
}
__device__ __forceinline__ float silu_f(float x) { return x / (1.f + __expf(-x)); }

// ---------------- K1: repack conv weights to bf16 im2col ----------------
__global__ void __launch_bounds__(256) prep_weights_kernel(const float* __restrict__ w0,
                                                           const float* __restrict__ w1) {
    int idx = blockIdx.x * 256 + threadIdx.x;
    if (idx < 512 * 768) {
        int o = idx / 768, k = idx % 768, dk = k / 256, c = k % 256;
        g_A0[idx] = __float2bfloat16(w0[(o * 256 + c) * 3 + dk]);
    } else {
        int i2 = idx - 512 * 768;
        if (i2 < 256 * 1536) {
            int o = i2 / 1536, k = i2 % 1536, dk = k / 512, c = k % 512;
            g_A1[i2] = __float2bfloat16(w1[(o * 512 + c) * 3 + dk]);
        }
    }
}

// ---------------- K2: exact selection (radix top-k, jax tie semantics) ------
__device__ void radix_topk(uint32_t* skey, int limit, int K, int* hist,
                           uint32_t* ctl_pref, int* ctl_rem, int* ctl_cnt,
                           uint32_t* p_thr, int* p_cntgt) {
    const int tid = threadIdx.x;
    if (tid == 0) { *ctl_pref = 0u; *ctl_rem = K; *ctl_cnt = 0; }
    __syncthreads();
    for (int shift = 24; shift >= 0; shift -= 8) {
        hist[tid] = 0;
        __syncthreads();
        uint32_t pref  = *ctl_pref;
        uint32_t hmask = (shift == 24) ? 0u : (0xFFFFFFFFu << (shift + 8));
        for (int i = tid; i < limit; i += 256) {
            uint32_t k = skey[i];
            if (((k ^ pref) & hmask) == 0u) atomicAdd(&hist[(k >> shift) & 255], 1);
        }
        __syncthreads();
        if (tid == 0) {
            int accv = 0, b = 255;
            for (; b > 0; b--) {
                if (accv + hist[b] >= *ctl_rem) break;
                accv += hist[b];
            }
            *ctl_pref = pref | ((uint32_t)b << shift);
            *ctl_rem -= accv;
            *ctl_cnt += accv;
        }
        __syncthreads();
    }
    *p_thr = *ctl_pref;
    *p_cntgt = *ctl_cnt;
    __syncthreads();
}

__global__ void __launch_bounds__(256) select_kernel(const float* __restrict__ scores) {
    __shared__ uint32_t      s_key [SEQ];
    __shared__ unsigned char s_mask[SEQ];
    __shared__ int           s_scan[257];
    __shared__ int           s_hist[256];
    __shared__ uint32_t      s_pref;
    __shared__ int           s_rem, s_cnt;

    const int head = blockIdx.x, tid = threadIdx.x;
    const float* sc = scores + (size_t)head * SEQ;
    for (int i = tid; i < SEQ; i += 256) {
        uint32_t b = __float_as_uint(sc[i]);
        s_key[i] = (b & 0x80000000u) ? ~b : (b | 0x80000000u);
        s_mask[i] = 0;
    }
    __syncthreads();

    uint32_t thr; int cgt;
    radix_topk(s_key, SEQ - LOCQ, KTOP, s_hist, &s_pref, &s_rem, &s_cnt, &thr, &cgt);
    for (int i = tid; i < SEQ - LOCQ; i += 256)
        if (s_key[i] > thr) s_mask[i] = 1;
    for (int i = SEQ - LOCQ + tid; i < SEQ; i += 256) s_mask[i] = 1;
    __syncthreads();
    if (tid == 0) {
        int need = KTOP - cgt, taken = 0;
        for (int i = 0; i < SEQ - LOCQ && taken < need; i++)
            if (s_key[i] == thr) { s_mask[i] = 1; taken++; }
    }
    __syncthreads();

    const int base = tid * 32;
    int cnt = 0;
#pragma unroll
    for (int j = 0; j < 32; j++) cnt += s_mask[base + j];
    s_scan[tid] = cnt;
    __syncthreads();
    if (tid == 0) {
        int a = 0;
        for (int k = 0; k < 256; k++) { int t = s_scan[k]; s_scan[k] = a; a += t; }
    }
    __syncthreads();
    {
        int ho = s_scan[tid], no = base - s_scan[tid];
        for (int j = 0; j < 32; j++) {
            int i = base + j;
            if (s_mask[i]) { g_hh[head * KEEP + (ho++)] = i; }
            else { g_noninv[head * SEQ + i] = no; g_non[head * SP + (no++)] = i; }
        }
    }
    __syncthreads();

    for (int i = tid; i < SEQ; i += 256)
        if (s_mask[i]) s_key[i] = 0u;
    __syncthreads();
    uint32_t thr2; int cgt2;
    radix_topk(s_key, SEQ, 256, s_hist, &s_pref, &s_rem, &s_cnt, &thr2, &cgt2);
    for (int i = tid; i < SEQ; i += 256)
        s_mask[i] = (s_key[i] > thr2) ? 1 : 0;
    __syncthreads();
    if (tid == 0) {
        int need = 256 - cgt2, taken = 0;
        for (int i = 0; i < SEQ && taken < need; i++)
            if (s_key[i] == thr2) { s_mask[i] = 1; taken++; }
    }
    __syncthreads();
    cnt = 0;
#pragma unroll
    for (int j = 0; j < 32; j++) cnt += s_mask[base + j];
    s_scan[tid] = cnt;
    __syncthreads();
    if (tid == 0) {
        int a = 0;
        for (int k = 0; k < 256; k++) { int t = s_scan[k]; s_scan[k] = a; a += t; }
    }
    __syncthreads();
    {
        int ro = s_scan[tid];
        for (int j = 0; j < 32; j++) {
            int i = base + j;
            if (s_mask[i]) g_res[head * 256 + (ro++)] = g_noninv[head * SEQ + i];
        }
    }
}

// ---------------- K3: gather non_k|non_v -> X[t][256] (row copy) ------------
__global__ void __launch_bounds__(256) gather_x_kernel(const float* __restrict__ pk,
                                                       const float* __restrict__ pv) {
    const int head = blockIdx.y;
    const int t0 = blockIdx.x * 128;
    const int tid = threadIdx.x;
    __shared__ int pos[128];
    if (tid < 128) pos[tid] = g_non[head * SP + t0 + tid];
    __syncthreads();
    const int c2 = (tid & 63) * 2;
    const int r4 = tid >> 6;
    for (int r = r4; r < 128; r += 4) {
        size_t src = ((size_t)head * SEQ + pos[r]) * HD + c2;
        float2 vk = *(const float2*)(pk + src);
        float2 vv = *(const float2*)(pv + src);
        __nv_bfloat16* dst = g_X + ((size_t)head * SP + t0 + r) * 256;
        *(__nv_bfloat162*)(dst + c2)       = __nv_bfloat162(__float2bfloat16(vk.x), __float2bfloat16(vk.y));
        *(__nv_bfloat162*)(dst + 128 + c2) = __nv_bfloat162(__float2bfloat16(vv.x), __float2bfloat16(vv.y));
    }
}

// ---------------- K4: exact fp32 hh gather to output rows [0,256) ----------
__global__ void __launch_bounds__(256) hh_out_kernel(const float* __restrict__ pk,
                                                     const float* __restrict__ pv,
                                                     float* __restrict__ out) {
    const int head = blockIdx.x, tid = threadIdx.x;
    __shared__ int pos[KEEP];
    if (tid < KEEP) pos[tid] = g_hh[head * KEEP + tid];
    __syncthreads();
    const size_t vofs = (size_t)BH * 512 * HD;
    for (int idx = tid; idx < KEEP * HD; idx += 256) {
        int j = idx >> 7, dd = idx & 127;
        size_t src = ((size_t)head * SEQ + pos[j]) * HD + dd;
        size_t dst = ((size_t)head * 512 + j) * HD + dd;
        out[dst] = pk[src];
        out[vofs + dst] = pv[src];
    }
}

// ---------------- K5/K6: conv GEMM, [t][c] layout, cp.async 2-stage --------
template <int CIN, int MTOT>
__global__ void __launch_bounds__(256) conv_gemm_kernel(const float* __restrict__ bias) {
    constexpr int KTOT = 3 * CIN;
    constexpr int NI = KTOT / 32;
    const int head = blockIdx.z;
    const int m0 = blockIdx.y * 128;
    const int t0 = blockIdx.x * 128;
    const __nv_bfloat16* __restrict__ A   = (CIN == 256) ? g_A0 : g_A1;
    const __nv_bfloat16* __restrict__ Xh  = ((CIN == 256) ? g_X : g_Y0) + (size_t)head * SP * CIN;
    __nv_bfloat16* __restrict__       Yh  = ((CIN == 256) ? g_Y0 : g_L) + (size_t)head * SP * MTOT;

    __shared__ __align__(16) unsigned char sb[2 * 128 * 40 * 2 * 2];  // 40 KB
    typedef __nv_bfloat16 (*TileA)[128][40];
    TileA As = (TileA)sb;                 // As[2][128][40]  (m rows, k cols)
    TileA Bs = (TileA)(sb + 20480);       // Bs[2][128][40]  (n=t rows, k=c cols)
    typedef __nv_bfloat16 (*TileC)[136];
    TileC Cs = (TileC)sb;                 // Cs[128][136]    (t rows, c cols)

    const int tid = threadIdx.x, lane = tid & 31, wid = tid >> 5;
    const int wm = wid >> 2, wn = wid & 3;

    float acc[4][4][4];
#pragma unroll
    for (int i = 0; i < 4; i++)
#pragma unroll
        for (int j = 0; j < 4; j++)
#pragma unroll
            for (int k = 0; k < 4; k++) acc[i][j][k] = 0.f;

    auto issue = [&](int it, int b) {
        const int dk = (it * 32) / CIN;
        const int cbase = it * 32 - dk * CIN;
#pragma unroll
        for (int j = 0; j < 2; j++) {
            int q = tid + j * 256;
            int row = q >> 2, kc = (q & 3) * 8;
            cpa16(smem_u32(&As[b][row][kc]),
                  A + (size_t)(m0 + row) * KTOT + it * 32 + kc, 16);
        }
#pragma unroll
        for (int j = 0; j < 2; j++) {
            int q = tid + j * 256;
            int tl = q >> 2, kc = (q & 3) * 8;
            int tg = t0 + tl + dk - 1;
            int ok = (tg >= 0 && tg < SP) ? 16 : 0;
            int tc = (tg < 0) ? 0 : ((tg >= SP) ? SP - 1 : tg);
            cpa16(smem_u32(&Bs[b][tl][kc]),
                  Xh + (size_t)tc * CIN + cbase + kc, ok);
        }
        cpa_commit();
    };

    issue(0, 0);
    for (int i = 0; i < NI; i++) {
        const int b = i & 1;
        if (i + 1 < NI) {
            issue(i + 1, b ^ 1);
            asm volatile("cp.async.wait_group 1;");
        } else {
            asm volatile("cp.async.wait_group 0;");
        }
        __syncthreads();
#pragma unroll
        for (int ks = 0; ks < 2; ks++) {
            const int kr = ks * 16;
            uint32_t af[4][4], bfr[4][2];
#pragma unroll
            for (int mf = 0; mf < 4; mf++)
                ldsm_x4(af[mf], smem_u32(&As[b][wm * 64 + mf * 16 + (lane & 15)]
                                             [kr + ((lane & 16) ? 8 : 0)]));
#pragma unroll
            for (int nf = 0; nf < 4; nf++)
                ldsm_x2(bfr[nf], smem_u32(&Bs[b][wn * 32 + nf * 8 + (lane & 7)]
                                              [kr + ((lane & 8) ? 8 : 0)]));
#pragma unroll
            for (int mf = 0; mf < 4; mf++)
#pragma unroll
                for (int nf = 0; nf < 4; nf++)
                    mma16816(acc[mf][nf], af[mf], bfr[nf]);
        }
        __syncthreads();
    }

    // epilogue: bias + SiLU, transpose through smem, vectorized [t][c] store
#pragma unroll
    for (int mf = 0; mf < 4; mf++) {
#pragma unroll
        for (int half = 0; half < 2; half++) {
            int c = wm * 64 + mf * 16 + (lane >> 2) + half * 8;
            float bv = bias[m0 + c];
#pragma unroll
            for (int nf = 0; nf < 4; nf++) {
#pragma unroll
                for (int p = 0; p < 2; p++) {
                    int tl = wn * 32 + nf * 8 + (lane & 3) * 2 + p;
                    Cs[tl][c] = __float2bfloat16(silu_f(acc[mf][nf][half * 2 + p] + bv));
                }
            }
        }
    }
    __syncthreads();
#pragma unroll
    for (int j = 0; j < 8; j++) {
        int q = tid + j * 256;
        int row = q >> 4, col = (q & 15) * 8;
        uint4 v = *(const uint4*)&Cs[row][col];
        *(uint4*)(Yh + (size_t)(t0 + row) * MTOT + m0 + col) = v;
    }
}

// ---------------- K7a/b/c: column-wise softmax over t (per channel) --------
__global__ void __launch_bounds__(256) smax_partial_kernel() {
    const int head = blockIdx.y, chunk = blockIdx.x, c = threadIdx.x;
    const __nv_bfloat16* base = g_L + ((size_t)head * SP + chunk * 256) * 256 + c;
    float m = -1e30f;
    for (int t = 0; t < 256; t++)
        m = fmaxf(m, __bfloat162float(base[(size_t)t * 256]));
    float s = 0.f;
    for (int t = 0; t < 256; t++)
        s += __expf(__bfloat162float(base[(size_t)t * 256]) - m);
    g_pm[(head * NCHK + chunk) * 256 + c] = m;
    g_ps[(head * NCHK + chunk) * 256 + c] = s;
}

__global__ void __launch_bounds__(256) smax_reduce_kernel(const float* __restrict__ nz) {
    const int head = blockIdx.x, c = threadIdx.x;
    float M = -1e30f;
    for (int j = 0; j < NCHK; j++)
        M = fmaxf(M, g_pm[(head * NCHK + j) * 256 + c]);
    float S = 0.f;
    for (int j = 0; j < NCHK; j++)
        S += g_ps[(head * NCHK + j) * 256 + c] * __expf(g_pm[(head * NCHK + j) * 256 + c] - M);
    g_rm[head * 256 + c] = M;
    g_rs[head * 256 + c] = nz[0] / S;
}

__global__ void __launch_bounds__(256) smax_norm_kernel() {
    const int head = blockIdx.y, t0 = blockIdx.x * 128, c = threadIdx.x;
    const float M = g_rm[head * 256 + c];
    const float sc = g_rs[head * 256 + c];
    __nv_bfloat16* base = g_L + ((size_t)head * SP + t0) * 256 + c;
    for (int r = 0; r < 128; r++) {
        float x = __bfloat162float(base[(size_t)r * 256]);
        base[(size_t)r * 256] = __float2bfloat16(__expf(x - M) * sc);
    }
}

// ---------------- K8: merged GEMM C[mem][d] = sum_t w[t][mem] X[t][d] ------
__global__ void __launch_bounds__(256) merged_gemm_kernel(float* __restrict__ out) {
    constexpr int NI = SP / 32;
    const int head = blockIdx.z;
    const int m0 = blockIdx.y * 128;           // mem slot block
    const int nsel = blockIdx.x;               // 0 = keys, 1 = vals
    const int nch0 = nsel * 128;
    const __nv_bfloat16* __restrict__ Lh = g_L + (size_t)head * SP * 256;
    const __nv_bfloat16* __restrict__ Xh = g_X + (size_t)head * SP * 256;

    __shared__ __align__(16) __nv_bfloat16 AsT[2][32][136];  // [k=t][m=mem]
    __shared__ __align__(16) __nv_bfloat16 Bs [2][32][136];  // [k=t][n=d]

    const int tid = threadIdx.x, lane = tid & 31, wid = tid >> 5;
    const int wm = wid >> 2, wn = wid & 3;

    float acc[4][4][4];
#pragma unroll
    for (int i = 0; i < 4; i++)
#pragma unroll
        for (int j = 0; j < 4; j++)
#pragma unroll
            for (int k = 0; k < 4; k++) acc[i][j][k] = 0.f;

    auto issue = [&](int it, int b) {
        const int k0 = it * 32;
#pragma unroll
        for (int j = 0; j < 2; j++) {
            int q = tid + j * 256;
            int kr = q >> 4, c8 = (q & 15) * 8;
            cpa16(smem_u32(&AsT[b][kr][c8]), Lh + (size_t)(k0 + kr) * 256 + m0 + c8, 16);
        }
#pragma unroll
        for (int j = 0; j < 2; j++) {
            int q = tid + j * 256;
            int kr = q >> 4, c8 = (q & 15) * 8;
            cpa16(smem_u32(&Bs[b][kr][c8]), Xh + (size_t)(k0 + kr) * 256 + nch0 + c8, 16);
        }
        cpa_commit();
    };

    issue(0, 0);
    for (int i = 0; i < NI; i++) {
        const int b = i & 1;
        if (i + 1 < NI) {
            issue(i + 1, b ^ 1);
            asm volatile("cp.async.wait_group 1;");
        } else {
            asm volatile("cp.async.wait_group 0;");
        }
        __syncthreads();
#pragma unroll
        for (int ks = 0; ks < 2; ks++) {
            const int kr = ks * 16;
            uint32_t af[4][4], bfr[4][2];
#pragma unroll
            for (int mf = 0; mf < 4; mf++)
                ldsm_x4t(af[mf], smem_u32(&AsT[b][kr + (lane & 7) + ((lane & 16) ? 8 : 0)]
                                                [wm * 64 + mf * 16 + ((lane & 8) ? 8 : 0)]));
#pragma unroll
            for (int nf = 0; nf < 4; nf++)
                ldsm_x2t(bfr[nf], smem_u32(&Bs[b][kr + (lane & 15)][wn * 32 + nf * 8]));
#pragma unroll
            for (int mf = 0; mf < 4; mf++)
#pragma unroll
                for (int nf = 0; nf < 4; nf++)
                    mma16816(acc[mf][nf], af[mf], bfr[nf]);
        }
        __syncthreads();
    }

    const size_t vofs = (size_t)BH * 512 * HD;
    const size_t hofs = nsel ? vofs : 0;
#pragma unroll
    for (int mf = 0; mf < 4; mf++) {
        int gm = m0 + wm * 64 + mf * 16 + (lane >> 2);
#pragma unroll
        for (int half = 0; half < 2; half++) {
            int r = gm + half * 8;
            float* dst_row = out + hofs + ((size_t)head * 512 + 256 + r) * HD;
#pragma unroll
            for (int nf = 0; nf < 4; nf++) {
                int d = wn * 32 + nf * 8 + (lane & 3) * 2;
                dst_row[d + 0] = acc[mf][nf][half * 2 + 0];
                dst_row[d + 1] = acc[mf][nf][half * 2 + 1];
            }
        }
    }
}

// ---------------- K9: fp32 residual add (1 - normalizer) -------------------
__global__ void __launch_bounds__(256) residual_kernel(const float* __restrict__ pk,
                                                       const float* __restrict__ pv,
                                                       const float* __restrict__ norm,
                                                       float* __restrict__ out) {
    const int head = blockIdx.x, tid = threadIdx.x;
    const float c = 1.f - norm[0];
    const size_t vofs = (size_t)BH * 512 * HD;
    __shared__ int pos[256];
    if (tid < 256) pos[tid] = g_non[head * SP + g_res[head * 256 + tid]];
    __syncthreads();
    for (int idx = tid; idx < 256 * HD; idx += 256) {
        int m = idx >> 7, d = idx & 127;
        size_t src = ((size_t)head * SEQ + pos[m]) * HD + d;
        size_t dst = ((size_t)head * 512 + 256 + m) * HD + d;
        out[dst]        += c * pk[src];
        out[vofs + dst] += c * pv[src];
    }
}

// ---------------- launch ----------------
extern "C" void kernel_launch(void* const* d_in, const int* in_sizes, int n_in,
                              void* d_out, int out_size) {
    const float* pk = (const float*)d_in[0];
    const float* pv = (const float*)d_in[1];
    const float* sc = (const float*)d_in[2];
    const float* w0 = (const float*)d_in[3];
    const float* b0 = (const float*)d_in[4];
    const float* w1 = (const float*)d_in[5];
    const float* b1 = (const float*)d_in[6];
    const float* nz = (const float*)d_in[7];
    float* out = (float*)d_out;

    prep_weights_kernel<<<3072, 256>>>(w0, w1);
    select_kernel<<<64, 256>>>(sc);
    gather_x_kernel<<<dim3(62, 64), 256>>>(pk, pv);
    hh_out_kernel<<<64, 256>>>(pk, pv, out);
    conv_gemm_kernel<256, 512><<<dim3(62, 4, 64), 256>>>(b0);
    conv_gemm_kernel<512, 256><<<dim3(62, 2, 64), 256>>>(b1);
    smax_partial_kernel<<<dim3(NCHK, 64), 256>>>();
    smax_reduce_kernel<<<64, 256>>>(nz);
    smax_norm_kernel<<<dim3(62, 64), 256>>>();
    merged_gemm_kernel<<<dim3(2, 2, 64), 256>>>(out);
    residual_kernel<<<64, 256>>>(pk, pv, nz, out);
}

// round 12
// speedup vs baseline: 2.3138x; 1.3014x over previous
#include <cuda_runtime.h>
#include <cuda_bf16.h>
#include <cstdint>

#define BH   64
#define SEQ  8192
#define HD   128
#define SP   7936
#define KEEP 256
#define KTOP 192
#define LOCQ 64
#define NCHK 31     // SP / 256

// ---------------- scratch (device globals: allocation-free) ----------------
// Activations are TIME-MAJOR: row t holds all channels contiguously.
__device__ __align__(128) __nv_bfloat16 g_X [(size_t)BH * SP * 256];   // [head][t][256] (k|v)
__device__ __align__(128) __nv_bfloat16 g_Y0[(size_t)BH * SP * 512];   // [head][t][512]
__device__ __align__(128) __nv_bfloat16 g_L [(size_t)BH * SP * 256];   // [head][t][256]
__device__ __align__(128) __nv_bfloat16 g_A0[512 * 768];               // conv0 W, k = dk*256+c
__device__ __align__(128) __nv_bfloat16 g_A1[256 * 1536];              // conv1 W, k = dk*512+c
__device__ int   g_hh    [BH * KEEP];
__device__ int   g_non   [BH * SP];
__device__ int   g_res   [BH * 256];
__device__ int   g_noninv[BH * SEQ];
__device__ float g_pm [BH * NCHK * 256];                // partial max
__device__ float g_ps [BH * NCHK * 256];                // partial sum
__device__ float g_rm [BH * 256];                       // col max
__device__ float g_rs [BH * 256];                       // col scale = nz / sum

// ---------------- helpers ----------------
__device__ __forceinline__ uint32_t smem_u32(const void* p) {
    return (uint32_t)__cvta_generic_to_shared(p);
}
__device__ __forceinline__ void ldsm_x4(uint32_t* r, uint32_t a) {
    asm volatile("ldmatrix.sync.aligned.m8n8.x4.shared.b16 {%0,%1,%2,%3}, [%4];"
                 : "=r"(r[0]), "=r"(r[1]), "=r"(r[2]), "=r"(r[3]) : "r"(a));
}
__device__ __forceinline__ void ldsm_x4t(uint32_t* r, uint32_t a) {
    asm volatile("ldmatrix.sync.aligned.m8n8.x4.trans.shared.b16 {%0,%1,%2,%3}, [%4];"
                 : "=r"(r[0]), "=r"(r[1]), "=r"(r[2]), "=r"(r[3]) : "r"(a));
}
__device__ __forceinline__ void ldsm_x2t(uint32_t* r, uint32_t a) {
    asm volatile("ldmatrix.sync.aligned.m8n8.x2.trans.shared.b16 {%0,%1}, [%2];"
                 : "=r"(r[0]), "=r"(r[1]) : "r"(a));
}
__device__ __forceinline__ void ldsm_x2(uint32_t* r, uint32_t a) {
    asm volatile("ldmatrix.sync.aligned.m8n8.x2.shared.b16 {%0,%1}, [%2];"
                 : "=r"(r[0]), "=r"(r[1]) : "r"(a));
}
__device__ __forceinline__ void mma16816(float* c, const uint32_t* a, const uint32_t* b) {
    asm volatile(
        "mma.sync.aligned.m16n8k16.row.col.f32.bf16.bf16.f32 "
        "{%0,%1,%2,%3}, {%4,%5,%6,%7}, {%8,%9}, {%0,%1,%2,%3};\n"
        : "+f"(c[0]), "+f"(c[1]), "+f"(c[2]), "+f"(c[3])
        : "r"(a[0]), "r"(a[1]), "r"(a[2]), "r"(a[3]), "r"(b[0]), "r"(b[1]));
}
__device__ __forceinline__ void cpa16(uint32_t d, const void* s, int sz) {
    asm volatile("cp.async.cg.shared.global [%0], [%1], 16, %2;"
                 :: "r"(d), "l"(s), "r"(sz));
}
__device__ __forceinline__ void cpa_commit() {
    asm volatile("cp.async.commit_group;");
}
__device__ __forceinline__ void cpa_wait2() {
    asm volatile("cp.async.wait_group 2;");
}
__device__ __forceinline__ float silu_f(float x) { return x / (1.f + __expf(-x)); }

// ---------------- K1: repack conv weights to bf16 im2col ----------------
__global__ void __launch_bounds__(256) prep_weights_kernel(const float* __restrict__ w0,
                                                           const float* __restrict__ w1) {
    int idx = blockIdx.x * 256 + threadIdx.x;
    if (idx < 512 * 768) {
        int o = idx / 768, k = idx % 768, dk = k / 256, c = k % 256;
        g_A0[idx] = __float2bfloat16(w0[(o * 256 + c) * 3 + dk]);
    } else {
        int i2 = idx - 512 * 768;
        if (i2 < 256 * 1536) {
            int o = i2 / 1536, k = i2 % 1536, dk = k / 512, c = k % 512;
            g_A1[i2] = __float2bfloat16(w1[(o * 512 + c) * 3 + dk]);
        }
    }
}

// ---------------- K2: exact selection (radix top-k, jax tie semantics) ------
__device__ void radix_topk(uint32_t* skey, int limit, int K, int* hist,
                           uint32_t* ctl_pref, int* ctl_rem, int* ctl_cnt,
                           uint32_t* p_thr, int* p_cntgt) {
    const int tid = threadIdx.x;
    if (tid == 0) { *ctl_pref = 0u; *ctl_rem = K; *ctl_cnt = 0; }
    __syncthreads();
    for (int shift = 24; shift >= 0; shift -= 8) {
        hist[tid] = 0;
        __syncthreads();
        uint32_t pref  = *ctl_pref;
        uint32_t hmask = (shift == 24) ? 0u : (0xFFFFFFFFu << (shift + 8));
        for (int i = tid; i < limit; i += 256) {
            uint32_t k = skey[i];
            if (((k ^ pref) & hmask) == 0u) atomicAdd(&hist[(k >> shift) & 255], 1);
        }
        __syncthreads();
        if (tid == 0) {
            int accv = 0, b = 255;
            for (; b > 0; b--) {
                if (accv + hist[b] >= *ctl_rem) break;
                accv += hist[b];
            }
            *ctl_pref = pref | ((uint32_t)b << shift);
            *ctl_rem -= accv;
            *ctl_cnt += accv;
        }
        __syncthreads();
    }
    *p_thr = *ctl_pref;
    *p_cntgt = *ctl_cnt;
    __syncthreads();
}

__global__ void __launch_bounds__(256) select_kernel(const float* __restrict__ scores) {
    __shared__ uint32_t      s_key [SEQ];
    __shared__ unsigned char s_mask[SEQ];
    __shared__ int           s_scan[257];
    __shared__ int           s_hist[256];
    __shared__ uint32_t      s_pref;
    __shared__ int           s_rem, s_cnt;

    const int head = blockIdx.x, tid = threadIdx.x;
    const int base = tid * 32;
    const float* sc = scores + (size_t)head * SEQ;
    for (int i = tid; i < SEQ; i += 256) {
        uint32_t b = __float_as_uint(sc[i]);
        s_key[i] = (b & 0x80000000u) ? ~b : (b | 0x80000000u);
        s_mask[i] = 0;
    }
    __syncthreads();

    // parallel tie-fill: mark first `need` positions i < limit with key==thr
    auto tie_fill = [&](uint32_t thr, int need, int limit) {
        int eqc = 0;
#pragma unroll
        for (int j = 0; j < 32; j++) {
            int i = base + j;
            if (i < limit && s_key[i] == thr) eqc++;
        }
        s_scan[tid] = eqc;
        __syncthreads();
        if (tid == 0) {
            int a = 0;
            for (int k = 0; k < 256; k++) { int t = s_scan[k]; s_scan[k] = a; a += t; }
        }
        __syncthreads();
        int r = s_scan[tid];
        for (int j = 0; j < 32; j++) {
            int i = base + j;
            if (i < limit && s_key[i] == thr) {
                if (r < need) s_mask[i] = 1;
                r++;
            }
        }
        __syncthreads();
    };

    uint32_t thr; int cgt;
    radix_topk(s_key, SEQ - LOCQ, KTOP, s_hist, &s_pref, &s_rem, &s_cnt, &thr, &cgt);
    for (int i = tid; i < SEQ - LOCQ; i += 256)
        if (s_key[i] > thr) s_mask[i] = 1;
    for (int i = SEQ - LOCQ + tid; i < SEQ; i += 256) s_mask[i] = 1;
    __syncthreads();
    tie_fill(thr, KTOP - cgt, SEQ - LOCQ);

    int cnt = 0;
#pragma unroll
    for (int j = 0; j < 32; j++) cnt += s_mask[base + j];
    s_scan[tid] = cnt;
    __syncthreads();
    if (tid == 0) {
        int a = 0;
        for (int k = 0; k < 256; k++) { int t = s_scan[k]; s_scan[k] = a; a += t; }
    }
    __syncthreads();
    {
        int ho = s_scan[tid], no = base - s_scan[tid];
        for (int j = 0; j < 32; j++) {
            int i = base + j;
            if (s_mask[i]) { g_hh[head * KEEP + (ho++)] = i; }
            else { g_noninv[head * SEQ + i] = no; g_non[head * SP + (no++)] = i; }
        }
    }
    __syncthreads();

    for (int i = tid; i < SEQ; i += 256)
        if (s_mask[i]) s_key[i] = 0u;
    __syncthreads();
    uint32_t thr2; int cgt2;
    radix_topk(s_key, SEQ, 256, s_hist, &s_pref, &s_rem, &s_cnt, &thr2, &cgt2);
    for (int i = tid; i < SEQ; i += 256)
        s_mask[i] = (s_key[i] > thr2) ? 1 : 0;
    __syncthreads();
    tie_fill(thr2, 256 - cgt2, SEQ);

    cnt = 0;
#pragma unroll
    for (int j = 0; j < 32; j++) cnt += s_mask[base + j];
    s_scan[tid] = cnt;
    __syncthreads();
    if (tid == 0) {
        int a = 0;
        for (int k = 0; k < 256; k++) { int t = s_scan[k]; s_scan[k] = a; a += t; }
    }
    __syncthreads();
    {
        int ro = s_scan[tid];
        for (int j = 0; j < 32; j++) {
            int i = base + j;
            if (s_mask[i]) g_res[head * 256 + (ro++)] = g_noninv[head * SEQ + i];
        }
    }
}

// ---------------- K3: gather non_k|non_v -> X[t][256] (row copy) ------------
__global__ void __launch_bounds__(256) gather_x_kernel(const float* __restrict__ pk,
                                                       const float* __restrict__ pv) {
    const int head = blockIdx.y;
    const int t0 = blockIdx.x * 128;
    const int tid = threadIdx.x;
    __shared__ int pos[128];
    if (tid < 128) pos[tid] = g_non[head * SP + t0 + tid];
    __syncthreads();
    const int c2 = (tid & 63) * 2;
    const int r4 = tid >> 6;
    for (int r = r4; r < 128; r += 4) {
        size_t src = ((size_t)head * SEQ + pos[r]) * HD + c2;
        float2 vk = *(const float2*)(pk + src);
        float2 vv = *(const float2*)(pv + src);
        __nv_bfloat16* dst = g_X + ((size_t)head * SP + t0 + r) * 256;
        *(__nv_bfloat162*)(dst + c2)       = __nv_bfloat162(__float2bfloat16(vk.x), __float2bfloat16(vk.y));
        *(__nv_bfloat162*)(dst + 128 + c2) = __nv_bfloat162(__float2bfloat16(vv.x), __float2bfloat16(vv.y));
    }
}

// ---------------- K4: exact fp32 hh gather to output rows [0,256) ----------
__global__ void __launch_bounds__(256) hh_out_kernel(const float* __restrict__ pk,
                                                     const float* __restrict__ pv,
                                                     float* __restrict__ out) {
    const int head = blockIdx.x, tid = threadIdx.x;
    __shared__ int pos[KEEP];
    if (tid < KEEP) pos[tid] = g_hh[head * KEEP + tid];
    __syncthreads();
    const size_t vofs = (size_t)BH * 512 * HD;
    for (int idx = tid; idx < KEEP * HD; idx += 256) {
        int j = idx >> 7, dd = idx & 127;
        size_t src = ((size_t)head * SEQ + pos[j]) * HD + dd;
        size_t dst = ((size_t)head * 512 + j) * HD + dd;
        out[dst] = pk[src];
        out[vofs + dst] = pv[src];
    }
}

// ---------------- K5/K6: conv GEMM, 4-stage cp.async ring, 1 sync/iter -----
template <int CIN, int MTOT>
__global__ void __launch_bounds__(256, 2) conv_gemm_kernel(const float* __restrict__ bias) {
    constexpr int KTOT = 3 * CIN;
    constexpr int NI = KTOT / 32;
    constexpr int NS = 4;                 // pipeline stages
    const int head = blockIdx.z;
    const int m0 = blockIdx.y * 128;
    const int t0 = blockIdx.x * 128;
    const __nv_bfloat16* __restrict__ A   = (CIN == 256) ? g_A0 : g_A1;
    const __nv_bfloat16* __restrict__ Xh  = ((CIN == 256) ? g_X : g_Y0) + (size_t)head * SP * CIN;
    __nv_bfloat16* __restrict__       Yh  = ((CIN == 256) ? g_Y0 : g_L) + (size_t)head * SP * MTOT;

    extern __shared__ __align__(16) unsigned char sb[];   // 4 * 20480 = 81920 B
    // stage s: A tile [128][40] at s*20480, B tile [128][40] at s*20480 + 10240
    typedef __nv_bfloat16 Row40[40];
    typedef __nv_bfloat16 Row136[136];
    Row136* Cs = (Row136*)sb;             // epilogue alias: [128][136]

    const int tid = threadIdx.x, lane = tid & 31, wid = tid >> 5;
    const int wm = wid >> 2, wn = wid & 3;

    float acc[4][4][4];
#pragma unroll
    for (int i = 0; i < 4; i++)
#pragma unroll
        for (int j = 0; j < 4; j++)
#pragma unroll
            for (int k = 0; k < 4; k++) acc[i][j][k] = 0.f;

    auto issue = [&](int it, int s) {
        Row40* As = (Row40*)(sb + s * 20480);
        Row40* Bs = (Row40*)(sb + s * 20480 + 10240);
        const int dk = (it * 32) / CIN;
        const int cbase = it * 32 - dk * CIN;
#pragma unroll
        for (int j = 0; j < 2; j++) {
            int q = tid + j * 256;
            int row = q >> 2, kc = (q & 3) * 8;
            cpa16(smem_u32(&As[row][kc]),
                  A + (size_t)(m0 + row) * KTOT + it * 32 + kc, 16);
        }
#pragma unroll
        for (int j = 0; j < 2; j++) {
            int q = tid + j * 256;
            int tl = q >> 2, kc = (q & 3) * 8;
            int tg = t0 + tl + dk - 1;
            int ok = (tg >= 0 && tg < SP) ? 16 : 0;
            int tc = (tg < 0) ? 0 : ((tg >= SP) ? SP - 1 : tg);
            cpa16(smem_u32(&Bs[tl][kc]),
                  Xh + (size_t)tc * CIN + cbase + kc, ok);
        }
    };

#pragma unroll
    for (int it = 0; it < NS - 1; ++it) {
        issue(it, it);          // NI >= 24 > NS-1 always
        cpa_commit();
    }

    for (int i = 0; i < NI; i++) {
        cpa_wait2();            // stage i resident (each iter commits exactly 1 group)
        __syncthreads();
        const int s = i & 3;
        Row40* As = (Row40*)(sb + s * 20480);
        Row40* Bs = (Row40*)(sb + s * 20480 + 10240);
#pragma unroll
        for (int ks = 0; ks < 2; ks++) {
            const int kr = ks * 16;
            uint32_t af[4][4], bfr[4][2];
#pragma unroll
            for (int mf = 0; mf < 4; mf++)
                ldsm_x4(af[mf], smem_u32(&As[wm * 64 + mf * 16 + (lane & 15)]
                                            [kr + ((lane & 16) ? 8 : 0)]));
#pragma unroll
            for (int nf = 0; nf < 4; nf++)
                ldsm_x2(bfr[nf], smem_u32(&Bs[wn * 32 + nf * 8 + (lane & 7)]
                                             [kr + ((lane & 8) ? 8 : 0)]));
#pragma unroll
            for (int mf = 0; mf < 4; mf++)
#pragma unroll
                for (int nf = 0; nf < 4; nf++)
                    mma16816(acc[mf][nf], af[mf], bfr[nf]);
        }
        int nx = i + NS - 1;
        if (nx < NI) issue(nx, nx & 3);
        cpa_commit();           // pad with empty group at tail to keep wait constant valid
    }
    asm volatile("cp.async.wait_group 0;");
    __syncthreads();            // all compute done before Cs alias reuse

    // epilogue: bias + SiLU, transpose through smem, vectorized [t][c] store
#pragma unroll
    for (int mf = 0; mf < 4; mf++) {
#pragma unroll
        for (int half = 0; half < 2; half++) {
            int c = wm * 64 + mf * 16 + (lane >> 2) + half * 8;
            float bv = bias[m0 + c];
#pragma unroll
            for (int nf = 0; nf < 4; nf++) {
#pragma unroll
                for (int p = 0; p < 2; p++) {
                    int tl = wn * 32 + nf * 8 + (lane & 3) * 2 + p;
                    Cs[tl][c] = __float2bfloat16(silu_f(acc[mf][nf][half * 2 + p] + bv));
                }
            }
        }
    }
    __syncthreads();
#pragma unroll
    for (int j = 0; j < 8; j++) {
        int q = tid + j * 256;
        int row = q >> 4, col = (q & 15) * 8;
        uint4 v = *(const uint4*)&Cs[row][col];
        *(uint4*)(Yh + (size_t)(t0 + row) * MTOT + m0 + col) = v;
    }
}

// ---------------- K7a/b/c: column-wise softmax over t (per channel) --------
__global__ void __launch_bounds__(256) smax_partial_kernel() {
    const int head = blockIdx.y, chunk = blockIdx.x, c = threadIdx.x;
    const __nv_bfloat16* base = g_L + ((size_t)head * SP + chunk * 256) * 256 + c;
    float m = -1e30f;
    for (int t = 0; t < 256; t++)
        m = fmaxf(m, __bfloat162float(base[(size_t)t * 256]));
    float s = 0.f;
    for (int t = 0; t < 256; t++)
        s += __expf(__bfloat162float(base[(size_t)t * 256]) - m);
    g_pm[(head * NCHK + chunk) * 256 + c] = m;
    g_ps[(head * NCHK + chunk) * 256 + c] = s;
}

__global__ void __launch_bounds__(256) smax_reduce_kernel(const float* __restrict__ nz) {
    const int head = blockIdx.x, c = threadIdx.x;
    float M = -1e30f;
    for (int j = 0; j < NCHK; j++)
        M = fmaxf(M, g_pm[(head * NCHK + j) * 256 + c]);
    float S = 0.f;
    for (int j = 0; j < NCHK; j++)
        S += g_ps[(head * NCHK + j) * 256 + c] * __expf(g_pm[(head * NCHK + j) * 256 + c] - M);
    g_rm[head * 256 + c] = M;
    g_rs[head * 256 + c] = nz[0] / S;
}

__global__ void __launch_bounds__(256) smax_norm_kernel() {
    const int head = blockIdx.y, t0 = blockIdx.x * 128, c = threadIdx.x;
    const float M = g_rm[head * 256 + c];
    const float sc = g_rs[head * 256 + c];
    __nv_bfloat16* base = g_L + ((size_t)head * SP + t0) * 256 + c;
    for (int r = 0; r < 128; r++) {
        float x = __bfloat162float(base[(size_t)r * 256]);
        base[(size_t)r * 256] = __float2bfloat16(__expf(x - M) * sc);
    }
}

// ---------------- K8: merged GEMM, 4-stage ring, 1 sync/iter ---------------
__global__ void __launch_bounds__(256, 2) merged_gemm_kernel(float* __restrict__ out) {
    constexpr int NI = SP / 32;           // 248
    constexpr int NS = 4;
    const int head = blockIdx.z;
    const int m0 = blockIdx.y * 128;      // mem slot block
    const int nsel = blockIdx.x;          // 0 = keys, 1 = vals
    const int nch0 = nsel * 128;
    const __nv_bfloat16* __restrict__ Lh = g_L + (size_t)head * SP * 256;
    const __nv_bfloat16* __restrict__ Xh = g_X + (size_t)head * SP * 256;

    extern __shared__ __align__(16) unsigned char sb[];   // 4 * 17408 = 69632 B
    // stage s: AsT [32][136] at s*17408, Bs [32][136] at +8704
    typedef __nv_bfloat16 Row136[136];

    const int tid = threadIdx.x, lane = tid & 31, wid = tid >> 5;
    const int wm = wid >> 2, wn = wid & 3;

    float acc[4][4][4];
#pragma unroll
    for (int i = 0; i < 4; i++)
#pragma unroll
        for (int j = 0; j < 4; j++)
#pragma unroll
            for (int k = 0; k < 4; k++) acc[i][j][k] = 0.f;

    auto issue = [&](int it, int s) {
        Row136* AsT = (Row136*)(sb + s * 17408);
        Row136* Bs  = (Row136*)(sb + s * 17408 + 8704);
        const int k0 = it * 32;
#pragma unroll
        for (int j = 0; j < 2; j++) {
            int q = tid + j * 256;
            int kr = q >> 4, c8 = (q & 15) * 8;
            cpa16(smem_u32(&AsT[kr][c8]), Lh + (size_t)(k0 + kr) * 256 + m0 + c8, 16);
        }
#pragma unroll
        for (int j = 0; j < 2; j++) {
            int q = tid + j * 256;
            int kr = q >> 4, c8 = (q & 15) * 8;
            cpa16(smem_u32(&Bs[kr][c8]), Xh + (size_t)(k0 + kr) * 256 + nch0 + c8, 16);
        }
    };

#pragma unroll
    for (int it = 0; it < NS - 1; ++it) {
        issue(it, it);
        cpa_commit();
    }

    for (int i = 0; i < NI; i++) {
        cpa_wait2();
        __syncthreads();
        const int s = i & 3;
        Row136* AsT = (Row136*)(sb + s * 17408);
        Row136* Bs  = (Row136*)(sb + s * 17408 + 8704);
#pragma unroll
        for (int ks = 0; ks < 2; ks++) {
            const int kr = ks * 16;
            uint32_t af[4][4], bfr[4][2];
#pragma unroll
            for (int mf = 0; mf < 4; mf++)
                ldsm_x4t(af[mf], smem_u32(&AsT[kr + (lane & 7) + ((lane & 16) ? 8 : 0)]
                                              [wm * 64 + mf * 16 + ((lane & 8) ? 8 : 0)]));
#pragma unroll
            for (int nf = 0; nf < 4; nf++)
                ldsm_x2t(bfr[nf], smem_u32(&Bs[kr + (lane & 15)][wn * 32 + nf * 8]));
#pragma unroll
            for (int mf = 0; mf < 4; mf++)
#pragma unroll
                for (int nf = 0; nf < 4; nf++)
                    mma16816(acc[mf][nf], af[mf], bfr[nf]);
        }
        int nx = i + NS - 1;
        if (nx < NI) issue(nx, nx & 3);
        cpa_commit();
    }

    const size_t vofs = (size_t)BH * 512 * HD;
    const size_t hofs = nsel ? vofs : 0;
#pragma unroll
    for (int mf = 0; mf < 4; mf++) {
        int gm = m0 + wm * 64 + mf * 16 + (lane >> 2);
#pragma unroll
        for (int half = 0; half < 2; half++) {
            int r = gm + half * 8;
            float* dst_row = out + hofs + ((size_t)head * 512 + 256 + r) * HD;
#pragma unroll
            for (int nf = 0; nf < 4; nf++) {
                int d = wn * 32 + nf * 8 + (lane & 3) * 2;
                dst_row[d + 0] = acc[mf][nf][half * 2 + 0];
                dst_row[d + 1] = acc[mf][nf][half * 2 + 1];
            }
        }
    }
}

// ---------------- K9: fp32 residual add (1 - normalizer) -------------------
__global__ void __launch_bounds__(256) residual_kernel(const float* __restrict__ pk,
                                                       const float* __restrict__ pv,
                                                       const float* __restrict__ norm,
                                                       float* __restrict__ out) {
    const int head = blockIdx.x, tid = threadIdx.x;
    const float c = 1.f - norm[0];
    const size_t vofs = (size_t)BH * 512 * HD;
    __shared__ int pos[256];
    if (tid < 256) pos[tid] = g_non[head * SP + g_res[head * 256 + tid]];
    __syncthreads();
    for (int idx = tid; idx < 256 * HD; idx += 256) {
        int m = idx >> 7, d = idx & 127;
        size_t src = ((size_t)head * SEQ + pos[m]) * HD + d;
        size_t dst = ((size_t)head * 512 + 256 + m) * HD + d;
        out[dst]        += c * pk[src];
        out[vofs + dst] += c * pv[src];
    }
}

// ---------------- launch ----------------
extern "C" void kernel_launch(void* const* d_in, const int* in_sizes, int n_in,
                              void* d_out, int out_size) {
    const float* pk = (const float*)d_in[0];
    const float* pv = (const float*)d_in[1];
    const float* sc = (const float*)d_in[2];
    const float* w0 = (const float*)d_in[3];
    const float* b0 = (const float*)d_in[4];
    const float* w1 = (const float*)d_in[5];
    const float* b1 = (const float*)d_in[6];
    const float* nz = (const float*)d_in[7];
    float* out = (float*)d_out;

    cudaFuncSetAttribute(conv_gemm_kernel<256, 512>,
                         cudaFuncAttributeMaxDynamicSharedMemorySize, 81920);
    cudaFuncSetAttribute(conv_gemm_kernel<512, 256>,
                         cudaFuncAttributeMaxDynamicSharedMemorySize, 81920);
    cudaFuncSetAttribute(merged_gemm_kernel,
                         cudaFuncAttributeMaxDynamicSharedMemorySize, 69632);

    prep_weights_kernel<<<3072, 256>>>(w0, w1);
    select_kernel<<<64, 256>>>(sc);
    gather_x_kernel<<<dim3(62, 64), 256>>>(pk, pv);
    hh_out_kernel<<<64, 256>>>(pk, pv, out);
    conv_gemm_kernel<256, 512><<<dim3(62, 4, 64), 256, 81920>>>(b0);
    conv_gemm_kernel<512, 256><<<dim3(62, 2, 64), 256, 81920>>>(b1);
    smax_partial_kernel<<<dim3(NCHK, 64), 256>>>();
    smax_reduce_kernel<<<64, 256>>>(nz);
    smax_norm_kernel<<<dim3(62, 64), 256>>>();
    merged_gemm_kernel<<<dim3(2, 2, 64), 256, 69632>>>(out);
    residual_kernel<<<64, 256>>>(pk, pv, nz, out);
}